// round 8
// baseline (speedup 1.0000x reference)
#include <cuda_runtime.h>

// SceneEngine: closed-form subset-sum factorization.
//   Σ over non-empty subsets of exp(Σ_s exist[s,bit_s]) = Π_s(e0+e1) − Π_s e0
//   number_prob  -> elementary symmetric polynomial DP on Π_s(e0 + t·e1)
//   attr prob[d] -> (Π_s(e0 + e1·exp(a[s,d])) − Π_s e0) / Z
//
// R8: R7's barrier-free 5-role-warp structure + PER-WARP SMEM staging.
// Each warp coalesced-loads its own input slice (float4), __syncwarp,
// computes from SMEM, writes results to a per-warp SMEM out-buffer,
// __syncwarp, flushes coalesced. No __syncthreads anywhere.
//   block = 160 threads = 5 warps = 32 pairs:
//     w0: exist_prob + symmetric DP + number
//     w1: type D=5          w2: size D=6
//     w3: color pairs 0-15, d-halves (lane=(k<<1)|h)
//     w4: color pairs 16-31, d-halves

constexpr int NS = 9;

constexpr int OFF_EXIST  = 0;
constexpr int OFF_NUM    = 73728;
constexpr int OFF_TYPE   = 110592;
constexpr int OFF_NTYPE  = 135168;
constexpr int OFF_RTYPE  = 145408;
constexpr int OFF_SIZE   = 145664;
constexpr int OFF_NSIZE  = 174336;
constexpr int OFF_RSIZE  = 186624;
constexpr int OFF_COLOR  = 186880;
constexpr int OFF_NCOLOR = 231936;
constexpr int OFF_RCOLOR = 252416;

#define BIGF 3.402823466e+38f

// coalesced float4 copy by one warp
__device__ __forceinline__ void wcopy4(float* __restrict__ dst,
                                       const float* __restrict__ src,
                                       int n4, int lane)
{
    float4* __restrict__ d = (float4*)dst;
    const float4* __restrict__ s = (const float4*)src;
#pragma unroll 4
    for (int i = lane; i < n4; i += 32) d[i] = s[i];
}

__device__ __forceinline__ void exp_exist(const float* __restrict__ row,
                                          float e0[NS], float e1[NS])
{
#pragma unroll
    for (int s = 0; s < NS; s++) {
        e0[s] = __expf(row[2 * s + 0]);
        e1[s] = __expf(row[2 * s + 1]);
    }
}

__device__ __forceinline__ float min8(float v)
{
#pragma unroll
    for (int off = 4; off >= 1; off >>= 1)
        v = fminf(v, __shfl_xor_sync(0xFFFFFFFFu, v, off));
    return v;
}

// full-row attr role (type/size): lane = local pair, computes from SMEM,
// results into SMEM out-buffers, then coalesced flush.
template <int D>
__device__ __forceinline__ void attr_role(
    const float* __restrict__ s_attr,   // [32][9*D]
    const float* __restrict__ s_ex,     // [32][18]
    float* __restrict__ s_prob,         // [32][D+1]
    float* __restrict__ s_norm,         // [2][8][D]
    int lane, int blk,
    float* __restrict__ out,
    int off_prob, int off_norm, int off_rule)
{
    int k = lane & 15;
    int bloc = lane >> 4;

    float e0[NS], e1[NS];
    exp_exist(s_ex + lane * 18, e0, e1);

    float S0 = 1.0f, Zp = 1.0f;
#pragma unroll
    for (int s = 0; s < NS; s++) { S0 *= e0[s]; Zp *= (e0[s] + e1[s]); }
    float invZ = __fdividef(1.0f, Zp - S0);

    const float* __restrict__ a = s_attr + lane * NS * D;
    float p[D];
#pragma unroll
    for (int d = 0; d < D; d++) p[d] = 1.0f;
#pragma unroll
    for (int s = 0; s < NS; s++) {
#pragma unroll
        for (int d = 0; d < D; d++)
            p[d] *= fmaf(e1[s], __expf(a[s * D + d]), e0[s]);
    }

    float sum = 0.0f;
#pragma unroll
    for (int d = 0; d < D; d++) {
        p[d] = (p[d] - S0) * invZ;
        sum += p[d];
    }
    float nic = fminf(sum, 1.0f);

    float* __restrict__ op = s_prob + lane * (D + 1);
#pragma unroll
    for (int d = 0; d < D; d++) op[d] = p[d];
    op[D] = 1.0f - nic;

    if (k < 8) {
        float inv = __fdividef(1.0f, sum);
        float* __restrict__ on = s_norm + (bloc * 8 + k) * D;
#pragma unroll
        for (int d = 0; d < D; d++) on[d] = p[d] * inv;
    }

    float v = (k < 8) ? nic : BIGF;
    v = min8(v);
    if (k == 0) out[off_rule + blk * 2 + bloc] = v;

    __syncwarp();
    wcopy4(out + off_prob + (size_t)blk * 32 * (D + 1), s_prob, 32 * (D + 1) / 4, lane);
    wcopy4(out + off_norm + (size_t)blk * 16 * D,       s_norm, 16 * D / 4,       lane);
}

// color role for 16 pairs: lane = (k<<1)|h, h selects d-half (5 dims each)
__device__ __forceinline__ void color_role(
    const float* __restrict__ s_col,    // [16][90]
    const float* __restrict__ s_ex,     // [16][18]
    float* __restrict__ s_prob,         // [16][11]
    float* __restrict__ s_norm,         // [8][10]
    int lane, int b,
    float* __restrict__ out,
    int base_pair)                      // global pair idx of local pair 0
{
    int k = lane >> 1;
    int h = lane & 1;

    float e0[NS], e1[NS];
    exp_exist(s_ex + k * 18, e0, e1);

    float S0 = 1.0f, Zp = 1.0f;
#pragma unroll
    for (int s = 0; s < NS; s++) { S0 *= e0[s]; Zp *= (e0[s] + e1[s]); }
    float invZ = __fdividef(1.0f, Zp - S0);

    const float* __restrict__ a = s_col + k * 90 + h * 5;
    float p[5];
#pragma unroll
    for (int d = 0; d < 5; d++) p[d] = 1.0f;
#pragma unroll
    for (int s = 0; s < NS; s++) {
#pragma unroll
        for (int d = 0; d < 5; d++)
            p[d] *= fmaf(e1[s], __expf(a[s * 10 + d]), e0[s]);
    }

    float part = 0.0f;
#pragma unroll
    for (int d = 0; d < 5; d++) {
        p[d] = (p[d] - S0) * invZ;
        part += p[d];
    }
    float sum = part + __shfl_xor_sync(0xFFFFFFFFu, part, 1);
    float nic = fminf(sum, 1.0f);

    float* __restrict__ op = s_prob + k * 11 + h * 5;
#pragma unroll
    for (int d = 0; d < 5; d++) op[d] = p[d];
    if (h) op[5] = 1.0f - nic;          // element 10

    if (k < 8) {
        float inv = __fdividef(1.0f, sum);
        float* __restrict__ on = s_norm + k * 10 + h * 5;
#pragma unroll
        for (int d = 0; d < 5; d++) on[d] = p[d] * inv;
    }

    float v = (k < 8) ? nic : BIGF;
#pragma unroll
    for (int off = 16; off >= 1; off >>= 1)
        v = fminf(v, __shfl_xor_sync(0xFFFFFFFFu, v, off));
    if (lane == 0) out[OFF_RCOLOR + b] = v;

    __syncwarp();
    wcopy4(out + OFF_COLOR  + (size_t)base_pair * 11, s_prob, 44, lane);  // 176 floats
    wcopy4(out + OFF_NCOLOR + (size_t)b * 80,         s_norm, 20, lane);  // 80 floats
}

__global__ __launch_bounds__(160)
void scene_engine_kernel(const float* __restrict__ exist,
                         const float* __restrict__ typ,
                         const float* __restrict__ siz,
                         const float* __restrict__ col,
                         float* __restrict__ out)
{
    // per-warp SMEM regions (inputs + outputs); no block-level sharing
    __shared__ __align__(16) float s_ex0[576], s_ex1[576], s_ex2[576];
    __shared__ __align__(16) float s_ex3[288], s_ex4[288];
    __shared__ __align__(16) float s_ty[1440], s_si[1728];
    __shared__ __align__(16) float s_co3[1440], s_co4[1440];
    __shared__ __align__(16) float s_oex[576], s_onum[288];
    __shared__ __align__(16) float s_oty[192], s_onty[80];
    __shared__ __align__(16) float s_osi[224], s_onsi[96];
    __shared__ __align__(16) float s_oco3[176], s_onco3[80];
    __shared__ __align__(16) float s_oco4[176], s_onco4[80];

    int t = threadIdx.x;
    int w = t >> 5;
    int lane = t & 31;
    int blk = blockIdx.x;

    if (w == 0) {
        wcopy4(s_ex0, exist + (size_t)blk * 576, 144, lane);
        __syncwarp();

        float e0[NS], e1[NS];
        exp_exist(s_ex0 + lane * 18, e0, e1);

        float* __restrict__ oex = s_oex + lane * 18;
#pragma unroll
        for (int s = 0; s < NS; s++) {
            oex[2 * s + 0] = e0[s];
            oex[2 * s + 1] = e1[s];
        }

        // elementary symmetric polynomial DP
        float c[NS + 1];
        c[0] = 1.0f;
#pragma unroll
        for (int i = 1; i <= NS; i++) c[i] = 0.0f;
#pragma unroll
        for (int s = 0; s < NS; s++) {
#pragma unroll
            for (int j = NS; j >= 1; j--)
                c[j] = fmaf(c[j], e0[s], c[j - 1] * e1[s]);
            c[0] *= e0[s];
        }
        float Z = 0.0f;
#pragma unroll
        for (int j = 1; j <= NS; j++) Z += c[j];
        float invZ = __fdividef(1.0f, Z);

        float* __restrict__ onum = s_onum + lane * NS;
#pragma unroll
        for (int n = 0; n < NS; n++) onum[n] = c[n + 1] * invZ;

        __syncwarp();
        wcopy4(out + OFF_EXIST + (size_t)blk * 576, s_oex, 144, lane);
        wcopy4(out + OFF_NUM   + (size_t)blk * 288, s_onum, 72, lane);
    } else if (w == 1) {
        wcopy4(s_ty,  typ   + (size_t)blk * 1440, 360, lane);
        wcopy4(s_ex1, exist + (size_t)blk * 576,  144, lane);
        __syncwarp();
        attr_role<5>(s_ty, s_ex1, s_oty, s_onty, lane, blk, out,
                     OFF_TYPE, OFF_NTYPE, OFF_RTYPE);
    } else if (w == 2) {
        wcopy4(s_si,  siz   + (size_t)blk * 1728, 432, lane);
        wcopy4(s_ex2, exist + (size_t)blk * 576,  144, lane);
        __syncwarp();
        attr_role<6>(s_si, s_ex2, s_osi, s_onsi, lane, blk, out,
                     OFF_SIZE, OFF_NSIZE, OFF_RSIZE);
    } else if (w == 3) {
        wcopy4(s_co3, col   + (size_t)blk * 2880, 360, lane);
        wcopy4(s_ex3, exist + (size_t)blk * 576,   72, lane);
        __syncwarp();
        color_role(s_co3, s_ex3, s_oco3, s_onco3, lane, blk * 2 + 0, out,
                   blk * 32);
    } else {
        wcopy4(s_co4, col   + (size_t)blk * 2880 + 1440, 360, lane);
        wcopy4(s_ex4, exist + (size_t)blk * 576  + 288,   72, lane);
        __syncwarp();
        color_role(s_co4, s_ex4, s_oco4, s_onco4, lane, blk * 2 + 1, out,
                   blk * 32 + 16);
    }
}

extern "C" void kernel_launch(void* const* d_in, const int* in_sizes, int n_in,
                              void* d_out, int out_size)
{
    const float* exist = (const float*)d_in[0];
    const float* typ   = (const float*)d_in[1];
    const float* siz   = (const float*)d_in[2];
    const float* col   = (const float*)d_in[3];
    float* out = (float*)d_out;

    // 128 blocks × 160 threads (5 independent role warps per 32 pairs).
    scene_engine_kernel<<<128, 160>>>(exist, typ, siz, col, out);
}

// round 10
// speedup vs baseline: 1.0361x; 1.0361x over previous
#include <cuda_runtime.h>

// SceneEngine: closed-form subset-sum factorization.
//   Σ over non-empty subsets of exp(Σ_s exist[s,bit_s]) = Π_s(e0+e1) − Π_s e0
//   number_prob  -> elementary symmetric polynomial DP on Π_s(e0 + t·e1)
//   attr prob[d] -> (Π_s(e0 + e1·exp(a[s,d])) − Π_s e0) / Z
//
// R9 (re-bench; prior run was an infra failure): R7 structure (barrier-free,
// 5 role warps / 32 pairs, direct scattered GMEM access) + TWO-PHASE
// execution per role: front-load the whole input row set into register
// arrays (one exposed memory round-trip, MLP~60), then pure register
// compute. No SMEM, no syncthreads/syncwarp.
//   block = 160 threads = 5 warps = 32 pairs:
//     w0: exist_prob + symmetric DP + number
//     w1: type D=5 (lane=pair)      w2: size D=6 (lane=pair)
//     w3: color pairs 0-15, d-halves (lane=(k<<1)|h)
//     w4: color pairs 16-31, d-halves

constexpr int NS = 9;

constexpr int OFF_EXIST  = 0;
constexpr int OFF_NUM    = 73728;
constexpr int OFF_TYPE   = 110592;
constexpr int OFF_NTYPE  = 135168;
constexpr int OFF_RTYPE  = 145408;
constexpr int OFF_SIZE   = 145664;
constexpr int OFF_NSIZE  = 174336;
constexpr int OFF_RSIZE  = 186624;
constexpr int OFF_COLOR  = 186880;
constexpr int OFF_NCOLOR = 231936;
constexpr int OFF_RCOLOR = 252416;

#define BIGF 3.402823466e+38f

__device__ __forceinline__ float min8(float v)
{
#pragma unroll
    for (int off = 4; off >= 1; off >>= 1)
        v = fminf(v, __shfl_xor_sync(0xFFFFFFFFu, v, off));
    return v;
}

// full-row attr role (type/size): lane = local pair.
template <int D>
__device__ __forceinline__ void attr_full(
    const float* __restrict__ attr,
    const float* __restrict__ exist,
    int pair, int b, int k,
    float* __restrict__ out,
    int off_prob, int off_norm, int off_rule)
{
    // ---- phase 1: front-load everything (registers) ----
    float exr[2 * NS];
    {
        const float* __restrict__ r = exist + (size_t)pair * 18;
#pragma unroll
        for (int i = 0; i < 18; i++) exr[i] = r[i];
    }
    float ar[NS * D];
    {
        const float* __restrict__ a = attr + (size_t)pair * NS * D;
#pragma unroll
        for (int i = 0; i < NS * D; i++) ar[i] = a[i];
    }

    // ---- phase 2: pure register compute ----
    float e0[NS], e1[NS];
#pragma unroll
    for (int s = 0; s < NS; s++) {
        e0[s] = __expf(exr[2 * s + 0]);
        e1[s] = __expf(exr[2 * s + 1]);
    }
    float S0 = 1.0f, Zp = 1.0f;
#pragma unroll
    for (int s = 0; s < NS; s++) { S0 *= e0[s]; Zp *= (e0[s] + e1[s]); }
    float invZ = __fdividef(1.0f, Zp - S0);

    float p[D];
#pragma unroll
    for (int d = 0; d < D; d++) p[d] = 1.0f;
#pragma unroll
    for (int s = 0; s < NS; s++) {
#pragma unroll
        for (int d = 0; d < D; d++)
            p[d] *= fmaf(e1[s], __expf(ar[s * D + d]), e0[s]);
    }

    float sum = 0.0f;
#pragma unroll
    for (int d = 0; d < D; d++) {
        p[d] = (p[d] - S0) * invZ;
        sum += p[d];
    }
    float nic = fminf(sum, 1.0f);

    float* __restrict__ op = out + off_prob + (size_t)pair * (D + 1);
#pragma unroll
    for (int d = 0; d < D; d++) op[d] = p[d];
    op[D] = 1.0f - nic;

    if (k < 8) {
        float inv = __fdividef(1.0f, sum);
        float* __restrict__ on = out + off_norm + (size_t)(b * 8 + k) * D;
#pragma unroll
        for (int d = 0; d < D; d++) on[d] = p[d] * inv;
    }

    float v = (k < 8) ? nic : BIGF;
    v = min8(v);
    if (k == 0) out[off_rule + b] = v;   // lanes 0 & 16 (two b's)
}

// color role, d-split: warp covers 16 pairs (one b); lane=(k<<1)|h,
// each lane handles 5 of the 10 color dims.
__device__ __forceinline__ void color_half(
    const float* __restrict__ col,
    const float* __restrict__ exist,
    int pair_base, int lane,
    float* __restrict__ out)
{
    int k    = lane >> 1;
    int h    = lane & 1;
    int pair = pair_base + k;
    int b    = pair >> 4;

    // ---- phase 1: front-load ----
    float exr[2 * NS];
    {
        const float* __restrict__ r = exist + (size_t)pair * 18;
#pragma unroll
        for (int i = 0; i < 18; i++) exr[i] = r[i];
    }
    float ar[NS * 5];
    {
        const float* __restrict__ a = col + (size_t)pair * 90 + h * 5;
#pragma unroll
        for (int s = 0; s < NS; s++)
#pragma unroll
            for (int d = 0; d < 5; d++) ar[s * 5 + d] = a[s * 10 + d];
    }

    // ---- phase 2: compute ----
    float e0[NS], e1[NS];
#pragma unroll
    for (int s = 0; s < NS; s++) {
        e0[s] = __expf(exr[2 * s + 0]);
        e1[s] = __expf(exr[2 * s + 1]);
    }
    float S0 = 1.0f, Zp = 1.0f;
#pragma unroll
    for (int s = 0; s < NS; s++) { S0 *= e0[s]; Zp *= (e0[s] + e1[s]); }
    float invZ = __fdividef(1.0f, Zp - S0);

    float p[5];
#pragma unroll
    for (int d = 0; d < 5; d++) p[d] = 1.0f;
#pragma unroll
    for (int s = 0; s < NS; s++) {
#pragma unroll
        for (int d = 0; d < 5; d++)
            p[d] *= fmaf(e1[s], __expf(ar[s * 5 + d]), e0[s]);
    }

    float part = 0.0f;
#pragma unroll
    for (int d = 0; d < 5; d++) {
        p[d] = (p[d] - S0) * invZ;
        part += p[d];
    }
    float sum = part + __shfl_xor_sync(0xFFFFFFFFu, part, 1);
    float nic = fminf(sum, 1.0f);

    float* __restrict__ op = out + OFF_COLOR + (size_t)pair * 11 + h * 5;
#pragma unroll
    for (int d = 0; d < 5; d++) op[d] = p[d];
    if (h) op[5] = 1.0f - nic;           // element 10

    if (k < 8) {
        float inv = __fdividef(1.0f, sum);
        float* __restrict__ on = out + OFF_NCOLOR + (size_t)(b * 8 + k) * 10 + h * 5;
#pragma unroll
        for (int d = 0; d < 5; d++) on[d] = p[d] * inv;
    }

    float v = (k < 8) ? nic : BIGF;
#pragma unroll
    for (int off = 16; off >= 1; off >>= 1)
        v = fminf(v, __shfl_xor_sync(0xFFFFFFFFu, v, off));
    if (lane == 0) out[OFF_RCOLOR + b] = v;
}

__global__ __launch_bounds__(160)
void scene_engine_kernel(const float* __restrict__ exist,
                         const float* __restrict__ typ,
                         const float* __restrict__ siz,
                         const float* __restrict__ col,
                         float* __restrict__ out)
{
    int t = threadIdx.x;
    int w = t >> 5;
    int lane = t & 31;
    int blk = blockIdx.x;
    int pair = blk * 32 + lane;          // for w0..w2 (lane = local pair)
    int b = pair >> 4;
    int k = lane & 15;

    if (w == 0) {
        // ---- phase 1: front-load exist row ----
        float exr[2 * NS];
        {
            const float* __restrict__ r = exist + (size_t)pair * 18;
#pragma unroll
            for (int i = 0; i < 18; i++) exr[i] = r[i];
        }
        // ---- phase 2 ----
        float e0[NS], e1[NS];
#pragma unroll
        for (int s = 0; s < NS; s++) {
            e0[s] = __expf(exr[2 * s + 0]);
            e1[s] = __expf(exr[2 * s + 1]);
        }

        float* __restrict__ oex = out + OFF_EXIST + (size_t)pair * 18;
#pragma unroll
        for (int s = 0; s < NS; s++) {
            oex[2 * s + 0] = e0[s];
            oex[2 * s + 1] = e1[s];
        }

        // elementary symmetric polynomial DP
        float c[NS + 1];
        c[0] = 1.0f;
#pragma unroll
        for (int i = 1; i <= NS; i++) c[i] = 0.0f;
#pragma unroll
        for (int s = 0; s < NS; s++) {
#pragma unroll
            for (int j = NS; j >= 1; j--)
                c[j] = fmaf(c[j], e0[s], c[j - 1] * e1[s]);
            c[0] *= e0[s];
        }
        float Z = 0.0f;
#pragma unroll
        for (int j = 1; j <= NS; j++) Z += c[j];
        float invZ = __fdividef(1.0f, Z);

        float* __restrict__ onum = out + OFF_NUM + (size_t)pair * NS;
#pragma unroll
        for (int n = 0; n < NS; n++) onum[n] = c[n + 1] * invZ;
    } else if (w == 1) {
        attr_full<5>(typ, exist, pair, b, k, out, OFF_TYPE, OFF_NTYPE, OFF_RTYPE);
    } else if (w == 2) {
        attr_full<6>(siz, exist, pair, b, k, out, OFF_SIZE, OFF_NSIZE, OFF_RSIZE);
    } else if (w == 3) {
        color_half(col, exist, blk * 32, lane, out);
    } else {
        color_half(col, exist, blk * 32 + 16, lane, out);
    }
}

extern "C" void kernel_launch(void* const* d_in, const int* in_sizes, int n_in,
                              void* d_out, int out_size)
{
    const float* exist = (const float*)d_in[0];
    const float* typ   = (const float*)d_in[1];
    const float* siz   = (const float*)d_in[2];
    const float* col   = (const float*)d_in[3];
    float* out = (float*)d_out;

    // 128 blocks × 160 threads (5 role warps per 32 pairs), single wave.
    scene_engine_kernel<<<128, 160>>>(exist, typ, siz, col, out);
}

// round 11
// speedup vs baseline: 1.3538x; 1.3066x over previous
#include <cuda_runtime.h>

// SceneEngine: closed-form subset-sum factorization.
//   Σ over non-empty subsets of exp(Σ_s exist[s,bit_s]) = Π_s(e0+e1) − Π_s e0
//   number_prob  -> elementary symmetric polynomial DP on Π_s(e0 + t·e1)
//   attr prob[d] -> (Π_s(e0 + e1·exp(a[s,d])) − Π_s e0) / Z
//
// R11: 256 blocks (block = one b) × 160 threads = 16 pairs/block,
// 2 CTAs/SM -> 10 warps/SM. Every role warp split by dims so per-warp
// scattered loads <= 45. Barrier-free, direct GMEM (the pattern that wins).
//   w0: exist_prob + symmetric DP + number (16 active lanes, 18 loads)
//   w1: type  D=5, lane=(k<<1)|h, dims 3+2
//   w2: size  D=6, lane=(k<<1)|h, dims 3+3
//   w3: color D=10, pairs k=0-7, lane=(k<<2)|q, dims 3+3+3+1; norm+rule here
//   w4: color pairs k=8-15, prob only

constexpr int NS = 9;

constexpr int OFF_EXIST  = 0;
constexpr int OFF_NUM    = 73728;
constexpr int OFF_TYPE   = 110592;
constexpr int OFF_NTYPE  = 135168;
constexpr int OFF_RTYPE  = 145408;
constexpr int OFF_SIZE   = 145664;
constexpr int OFF_NSIZE  = 174336;
constexpr int OFF_RSIZE  = 186624;
constexpr int OFF_COLOR  = 186880;
constexpr int OFF_NCOLOR = 231936;
constexpr int OFF_RCOLOR = 252416;

#define BIGF 3.402823466e+38f

__device__ __forceinline__ void exp_exist(const float* __restrict__ r,
                                          float e0[NS], float e1[NS])
{
#pragma unroll
    for (int s = 0; s < NS; s++) {
        e0[s] = __expf(r[2 * s + 0]);
        e1[s] = __expf(r[2 * s + 1]);
    }
}

__device__ __forceinline__ float warp_min(float v)
{
#pragma unroll
    for (int off = 16; off >= 1; off >>= 1)
        v = fminf(v, __shfl_xor_sync(0xFFFFFFFFu, v, off));
    return v;
}

// type/size role: warp covers 16 pairs, lane=(k<<1)|h; h=0 -> dims [0,H0),
// h=1 -> dims [H0,D). norm for k<8; rule = min over k<8.
template <int D, int H0>
__device__ __forceinline__ void attr_split(
    const float* __restrict__ attr,
    const float* __restrict__ exist,
    int b, int lane,
    float* __restrict__ out,
    int off_prob, int off_norm, int off_rule)
{
    int k = lane >> 1;
    int h = lane & 1;
    int pair = b * 16 + k;
    int nd    = h ? (D - H0) : H0;       // <= 3
    int dbase = h ? H0 : 0;

    const float* __restrict__ er = exist + (size_t)pair * 18;
    float e0[NS], e1[NS];
    exp_exist(er, e0, e1);

    float S0 = 1.0f, Zp = 1.0f;
#pragma unroll
    for (int s = 0; s < NS; s++) { S0 *= e0[s]; Zp *= (e0[s] + e1[s]); }
    float invZ = __fdividef(1.0f, Zp - S0);

    const float* __restrict__ a = attr + (size_t)pair * NS * D + dbase;
    float p[3];
#pragma unroll
    for (int j = 0; j < 3; j++) p[j] = 1.0f;
#pragma unroll
    for (int s = 0; s < NS; s++) {
#pragma unroll
        for (int j = 0; j < 3; j++) {
            if (j < nd)
                p[j] *= fmaf(e1[s], __expf(a[s * D + j]), e0[s]);
        }
    }

    float part = 0.0f;
#pragma unroll
    for (int j = 0; j < 3; j++) {
        if (j < nd) {
            p[j] = (p[j] - S0) * invZ;
            part += p[j];
        }
    }
    float sum = part + __shfl_xor_sync(0xFFFFFFFFu, part, 1);
    float nic = fminf(sum, 1.0f);

    float* __restrict__ op = out + off_prob + (size_t)pair * (D + 1) + dbase;
#pragma unroll
    for (int j = 0; j < 3; j++)
        if (j < nd) op[j] = p[j];
    if (h) op[D - dbase] = 1.0f - nic;   // element D

    if (k < 8) {
        float inv = __fdividef(1.0f, sum);
        float* __restrict__ on = out + off_norm + (size_t)(b * 8 + k) * D + dbase;
#pragma unroll
        for (int j = 0; j < 3; j++)
            if (j < nd) on[j] = p[j] * inv;
    }

    float v = (k < 8) ? nic : BIGF;
    v = warp_min(v);
    if (lane == 0) out[off_rule + b] = v;
}

// color role: warp covers 8 pairs, lane=(k_loc<<2)|q; q<3 -> 3 dims at q*3,
// q==3 -> dim 9. LOWK warp (k=0-7) also writes norm + rule.
template <bool LOWK>
__device__ __forceinline__ void color_q(
    const float* __restrict__ col,
    const float* __restrict__ exist,
    int b, int lane,
    float* __restrict__ out)
{
    int q = lane & 3;
    int k = (lane >> 2) + (LOWK ? 0 : 8);
    int pair = b * 16 + k;
    int nd    = (q == 3) ? 1 : 3;
    int dbase = q * 3;

    const float* __restrict__ er = exist + (size_t)pair * 18;
    float e0[NS], e1[NS];
    exp_exist(er, e0, e1);

    float S0 = 1.0f, Zp = 1.0f;
#pragma unroll
    for (int s = 0; s < NS; s++) { S0 *= e0[s]; Zp *= (e0[s] + e1[s]); }
    float invZ = __fdividef(1.0f, Zp - S0);

    const float* __restrict__ a = col + (size_t)pair * 90 + dbase;
    float p[3];
#pragma unroll
    for (int j = 0; j < 3; j++) p[j] = 1.0f;
#pragma unroll
    for (int s = 0; s < NS; s++) {
#pragma unroll
        for (int j = 0; j < 3; j++) {
            if (j < nd)
                p[j] *= fmaf(e1[s], __expf(a[s * 10 + j]), e0[s]);
        }
    }

    float part = 0.0f;
#pragma unroll
    for (int j = 0; j < 3; j++) {
        if (j < nd) {
            p[j] = (p[j] - S0) * invZ;
            part += p[j];
        }
    }
    // sum across the 4 q-lanes of this pair
    part += __shfl_xor_sync(0xFFFFFFFFu, part, 1);
    part += __shfl_xor_sync(0xFFFFFFFFu, part, 2);
    float sum = part;
    float nic = fminf(sum, 1.0f);

    float* __restrict__ op = out + OFF_COLOR + (size_t)pair * 11 + dbase;
#pragma unroll
    for (int j = 0; j < 3; j++)
        if (j < nd) op[j] = p[j];
    if (q == 3) op[1] = 1.0f - nic;      // element 10 (= dbase 9 + 1)

    if (LOWK) {
        float inv = __fdividef(1.0f, sum);
        float* __restrict__ on = out + OFF_NCOLOR + (size_t)(b * 8 + k) * 10 + dbase;
#pragma unroll
        for (int j = 0; j < 3; j++)
            if (j < nd) on[j] = p[j] * inv;

        float v = warp_min(nic);         // min over the 8 pairs (k<8)
        if (lane == 0) out[OFF_RCOLOR + b] = v;
    }
}

__global__ __launch_bounds__(160)
void scene_engine_kernel(const float* __restrict__ exist,
                         const float* __restrict__ typ,
                         const float* __restrict__ siz,
                         const float* __restrict__ col,
                         float* __restrict__ out)
{
    int t = threadIdx.x;
    int w = t >> 5;
    int lane = t & 31;
    int b = blockIdx.x;

    if (w == 0) {
        if (lane < 16) {
            int pair = b * 16 + lane;
            const float* __restrict__ er = exist + (size_t)pair * 18;
            float e0[NS], e1[NS];
            exp_exist(er, e0, e1);

            float* __restrict__ oex = out + OFF_EXIST + (size_t)pair * 18;
#pragma unroll
            for (int s = 0; s < NS; s++)
                ((float2*)oex)[s] = make_float2(e0[s], e1[s]);

            // elementary symmetric polynomial DP
            float c[NS + 1];
            c[0] = 1.0f;
#pragma unroll
            for (int i = 1; i <= NS; i++) c[i] = 0.0f;
#pragma unroll
            for (int s = 0; s < NS; s++) {
#pragma unroll
                for (int j = NS; j >= 1; j--)
                    c[j] = fmaf(c[j], e0[s], c[j - 1] * e1[s]);
                c[0] *= e0[s];
            }
            float Z = 0.0f;
#pragma unroll
            for (int j = 1; j <= NS; j++) Z += c[j];
            float invZ = __fdividef(1.0f, Z);

            float* __restrict__ onum = out + OFF_NUM + (size_t)pair * NS;
#pragma unroll
            for (int n = 0; n < NS; n++) onum[n] = c[n + 1] * invZ;
        }
    } else if (w == 1) {
        attr_split<5, 3>(typ, exist, b, lane, out, OFF_TYPE, OFF_NTYPE, OFF_RTYPE);
    } else if (w == 2) {
        attr_split<6, 3>(siz, exist, b, lane, out, OFF_SIZE, OFF_NSIZE, OFF_RSIZE);
    } else if (w == 3) {
        color_q<true>(col, exist, b, lane, out);
    } else {
        color_q<false>(col, exist, b, lane, out);
    }
}

extern "C" void kernel_launch(void* const* d_in, const int* in_sizes, int n_in,
                              void* d_out, int out_size)
{
    const float* exist = (const float*)d_in[0];
    const float* typ   = (const float*)d_in[1];
    const float* siz   = (const float*)d_in[2];
    const float* col   = (const float*)d_in[3];
    float* out = (float*)d_out;

    // 256 blocks (one b each) × 160 threads: 2 CTAs/SM, 10 warps/SM.
    scene_engine_kernel<<<256, 160>>>(exist, typ, siz, col, out);
}